// round 7
// baseline (speedup 1.0000x reference)
#include <cuda_runtime.h>
#include <cuda_fp16.h>
#include <mma.h>
using namespace nvcuda;

// ---------------- problem constants ----------------
#define NMAX 50000
#define EMAX 1600000
#define KDIM 128

// ---------------- device scratch ----------------
__device__ float2 g_degc[NMAX];              // .x = deg (float), .y = cnt (int bits)
__device__ float  g_dinv[NMAX];
__device__ int    g_cnt [NMAX];
__device__ int    g_off [NMAX];
__device__ int    g_rank[EMAX];              // within-bucket rank of each edge
__device__ int2   g_csr [EMAX];              // (src, norm-as-bits), bucketed by dst
__device__ int    g_bsum[256];
__device__ int    g_is64;
__device__ uint4  g_a16 [NMAX * KDIM / 8];   // fp16 activations (GEMM input)
__device__ uint4  g_hh  [NMAX * KDIM / 8];   // fp16 GEMM output (gather input)
__device__ uint4  g_w16 [5120];              // fp16 W1(2048) W2(2048) W3(1024) uint4s

// ---------------- fused init + dtype detect ----------------
__global__ void k_init(const void* __restrict__ ei, int n) {
    int i = blockIdx.x * blockDim.x + threadIdx.x;
    if (i < n) g_degc[i] = make_float2(1.0f, 0.0f);   // deg=1 (self loop), cnt=0
    if (i == 0) {
        const long long* p = (const long long*)ei;
        int ok = 1;
#pragma unroll
        for (int t = 0; t < 16; t++) {
            long long v = p[t];
            if (v < 0 || v >= (long long)n) ok = 0;
        }
        g_is64 = ok;
    }
}

// ---------------- fp32 -> fp16 conversion: x and all weights ----------------
__device__ inline uint4 pack8(float4 a, float4 b) {
    __half2 h0 = __floats2half2_rn(a.x, a.y), h1 = __floats2half2_rn(a.z, a.w);
    __half2 h2 = __floats2half2_rn(b.x, b.y), h3 = __floats2half2_rn(b.z, b.w);
    uint4 u;
    u.x = *(unsigned*)&h0; u.y = *(unsigned*)&h1;
    u.z = *(unsigned*)&h2; u.w = *(unsigned*)&h3;
    return u;
}

__global__ void k_prep(const float4* __restrict__ x,
                       const float4* __restrict__ W1,
                       const float4* __restrict__ W2,
                       const float4* __restrict__ W3, int n) {
    int i = blockIdx.x * blockDim.x + threadIdx.x;
    int nx = n * 16;
    if (i < nx) {
        g_a16[i] = pack8(x[2 * i], x[2 * i + 1]);
    } else {
        int j = i - nx;
        if (j < 5120) {
            const float4* src; int jj;
            if (j < 2048)      { src = W1; jj = j; }
            else if (j < 4096) { src = W2; jj = j - 2048; }
            else               { src = W3; jj = j - 4096; }
            g_w16[j] = pack8(src[2 * jj], src[2 * jj + 1]);
        }
    }
}

// ---------------- edge pass 1: degree + counts + rank ----------------
__global__ void k_edge_deg(const void* __restrict__ ei,
                           const float* __restrict__ ew, int E, int n) {
    int e = blockIdx.x * blockDim.x + threadIdx.x;
    if (e >= E) return;
    int s, d;
    if (g_is64) {
        const long long* p = (const long long*)ei;
        s = (int)p[e]; d = (int)p[E + e];
    } else {
        const int* p = (const int*)ei;
        s = p[e]; d = p[E + e];
    }
    if ((unsigned)s >= (unsigned)n || (unsigned)d >= (unsigned)n) { g_rank[e] = -1; return; }
    atomicAdd(&g_degc[d].x, ew[e]);                       // same 8B line as cnt
    int r = atomicAdd((int*)&g_degc[d].y, 1);
    g_rank[e] = r;
}

// ---------------- scan reduce (+ fused dinv + cnt unpack) ----------------
__global__ void k_scan_reduce(int n) {
    __shared__ int s[512];
    int t = threadIdx.x, i = blockIdx.x * 512 + t;
    int c = 0;
    if (i < n) {
        float2 v = g_degc[i];
        g_dinv[i] = rsqrtf(v.x);
        c = __float_as_int(v.y);
        g_cnt[i] = c;
    }
    s[t] = c;
    __syncthreads();
    for (int st = 256; st > 0; st >>= 1) {
        if (t < st) s[t] += s[t + st];
        __syncthreads();
    }
    if (t == 0) g_bsum[blockIdx.x] = s[0];
}

// scan within chunk + inline prefix over preceding chunk sums
__global__ void k_scan_chunks(int n) {
    __shared__ int s[512];
    __shared__ int base;
    int t = threadIdx.x, i = blockIdx.x * 512 + t;
    if (t == 0) base = 0;
    __syncthreads();
    int partial = 0;
    for (int j = t; j < blockIdx.x; j += 512) partial += g_bsum[j];
    if (partial) atomicAdd(&base, partial);
    int v = (i < n) ? g_cnt[i] : 0;
    s[t] = v;
    __syncthreads();
    for (int st = 1; st < 512; st <<= 1) {
        int add = (t >= st) ? s[t - st] : 0;
        __syncthreads();
        s[t] += add;
        __syncthreads();
    }
    if (i < n) g_off[i] = s[t] - v + base;
}

// ---------------- edge pass 2: fill CSR (no atomics) ----------------
__global__ void k_edge_fill(const void* __restrict__ ei,
                            const float* __restrict__ ew, int E) {
    int e = blockIdx.x * blockDim.x + threadIdx.x;
    if (e >= E) return;
    int r = g_rank[e];
    if (r < 0) return;
    int s, d;
    if (g_is64) {
        const long long* p = (const long long*)ei;
        s = (int)p[e]; d = (int)p[E + e];
    } else {
        const int* p = (const int*)ei;
        s = p[e]; d = p[E + e];
    }
    float nrm = g_dinv[s] * ew[e] * g_dinv[d];
    g_csr[g_off[d] + r] = make_int2(s, __float_as_int(nrm));
}

// ---------------- tensor-core GEMM: C[M,N] = A16[M,128] @ W16[128,N] ----------------
template<int N>
__global__ void __launch_bounds__(256)
k_hgemm(int woff_u4, int M) {
    constexpr int BM  = 64;
    constexpr int LDA = 136;
    constexpr int WN  = N / 2;
    constexpr int NT  = WN / 16;
    constexpr int ABYTES = BM * LDA * 2;
    constexpr int SBYTES = 8 * 16 * WN * 4;
    __shared__ __align__(16) char sraw[(ABYTES > SBYTES) ? ABYTES : SBYTES];
    __half (*As)[LDA] = (__half(*)[LDA])sraw;
    float*  stage     = (float*)sraw;

    const __half* Wg = (const __half*)g_w16 + (long)woff_u4 * 8;

    const int tid  = threadIdx.x;
    const int wid  = tid >> 5, lane = tid & 31;
    const int wrow = wid >> 1, wcol = wid & 1;
    const int rb   = blockIdx.x * BM;

    for (int i = tid; i < BM * 16; i += 256) {
        int r = i >> 4, c = i & 15;
        uint4 v = make_uint4(0u, 0u, 0u, 0u);
        if (rb + r < M) v = g_a16[(long)(rb + r) * 16 + c];
        *(uint4*)&As[r][c * 8] = v;
    }
    __syncthreads();

    wmma::fragment<wmma::accumulator, 16, 16, 16, float> acc[NT];
#pragma unroll
    for (int j = 0; j < NT; j++) wmma::fill_fragment(acc[j], 0.0f);

    wmma::fragment<wmma::matrix_a, 16, 16, 16, __half, wmma::row_major> af;
    wmma::fragment<wmma::matrix_b, 16, 16, 16, __half, wmma::row_major> bf;
#pragma unroll
    for (int k = 0; k < 8; k++) {
        wmma::load_matrix_sync(af, &As[wrow * 16][k * 16], LDA);
#pragma unroll
        for (int j = 0; j < NT; j++) {
            wmma::load_matrix_sync(bf, Wg + (long)(k * 16) * N + wcol * WN + j * 16, N);
            wmma::mma_sync(acc[j], af, bf, acc[j]);
        }
    }
    __syncthreads();

    float* st = stage + wid * 16 * WN;
#pragma unroll
    for (int j = 0; j < NT; j++)
        wmma::store_matrix_sync(st + j * 16, acc[j], WN, wmma::mem_row_major);
    __syncwarp();

    const int r0 = rb + wrow * 16;
    unsigned* outh = (unsigned*)g_hh;
    for (int i = lane; i < 16 * WN / 2; i += 32) {
        int r = (i * 2) / WN, c = (i * 2) % WN;
        int gr = r0 + r;
        if (gr < M) {
            __half2 h = __floats2half2_rn(st[r * WN + c], st[r * WN + c + 1]);
            outh[((long)gr * N + wcol * WN + c) >> 1] = *(unsigned*)&h;
        }
    }
}

// ---------------- sparse aggregation, fp16 features, F=128 ----------------
// Warp per node; CSR entries staged 32-at-a-time into smem (coalesced).
__global__ void __launch_bounds__(256) k_gather_h(const float* __restrict__ bias, int n) {
    __shared__ int2 ents[8][32];
    const int wslot = threadIdx.x >> 5;
    const int lane  = threadIdx.x & 31;
    const int node  = (blockIdx.x * 256 + threadIdx.x) >> 5;
    if (node >= n) return;

    const uint2* hh = (const uint2*)g_hh;

    float di = g_dinv[node];
    float sl = di * di;

    uint2 selfv = hh[(long)node * 32 + lane];
    __half2 s0 = *(__half2*)&selfv.x, s1 = *(__half2*)&selfv.y;
    float2 f0 = __half22float2(s0), f1 = __half22float2(s1);
    float ax = f0.x * sl, ay = f0.y * sl, az = f1.x * sl, aw = f1.y * sl;

    const int o = g_off[node];
    const int c = g_cnt[node];
    for (int k0 = 0; k0 < c; k0 += 32) {
        int rem = c - k0;
        int m = rem < 32 ? rem : 32;
        if (lane < m) ents[wslot][lane] = g_csr[o + k0 + lane];
        __syncwarp();
#pragma unroll 4
        for (int j = 0; j < m; j++) {
            int2 sp = ents[wslot][j];
            float nrm = __int_as_float(sp.y);
            uint2 hv = hh[(long)sp.x * 32 + lane];
            __half2 h0 = *(__half2*)&hv.x, h1 = *(__half2*)&hv.y;
            float2 g0 = __half22float2(h0), g1 = __half22float2(h1);
            ax = fmaf(g0.x, nrm, ax);
            ay = fmaf(g0.y, nrm, ay);
            az = fmaf(g1.x, nrm, az);
            aw = fmaf(g1.y, nrm, aw);
        }
        __syncwarp();
    }
    float4 bv = *(const float4*)(bias + lane * 4);
    float rx = fmaxf(ax + bv.x, 0.f);
    float ry = fmaxf(ay + bv.y, 0.f);
    float rz = fmaxf(az + bv.z, 0.f);
    float rw = fmaxf(aw + bv.w, 0.f);
    __half2 o0 = __floats2half2_rn(rx, ry), o1 = __floats2half2_rn(rz, rw);
    uint2 u; u.x = *(unsigned*)&o0; u.y = *(unsigned*)&o1;
    ((uint2*)g_a16)[(long)node * 32 + lane] = u;
}

// ---------------- sparse aggregation, fp16, F=64 (final, fp32 out) ----------------
__global__ void __launch_bounds__(256) k_gather_h64(const float* __restrict__ bias,
                                                    float* __restrict__ outp, int n) {
    __shared__ int2 ents[8][32];
    const int wslot = threadIdx.x >> 5;
    const int lane  = threadIdx.x & 31;
    const int node  = (blockIdx.x * 256 + threadIdx.x) >> 5;
    if (node >= n) return;

    const unsigned* hh = (const unsigned*)g_hh;   // half2 units, 32 per node

    float di = g_dinv[node];
    float sl = di * di;

    unsigned selfv = hh[(long)node * 32 + lane];
    float2 f = __half22float2(*(__half2*)&selfv);
    float ax = f.x * sl, ay = f.y * sl;

    const int o = g_off[node];
    const int c = g_cnt[node];
    for (int k0 = 0; k0 < c; k0 += 32) {
        int rem = c - k0;
        int m = rem < 32 ? rem : 32;
        if (lane < m) ents[wslot][lane] = g_csr[o + k0 + lane];
        __syncwarp();
#pragma unroll 4
        for (int j = 0; j < m; j++) {
            int2 sp = ents[wslot][j];
            float nrm = __int_as_float(sp.y);
            unsigned hv = hh[(long)sp.x * 32 + lane];
            float2 g = __half22float2(*(__half2*)&hv);
            ax = fmaf(g.x, nrm, ax);
            ay = fmaf(g.y, nrm, ay);
        }
        __syncwarp();
    }
    float2 bv = *(const float2*)(bias + lane * 2);
    *(float2*)(outp + (long)node * 64 + lane * 2) = make_float2(ax + bv.x, ay + bv.y);
}

// ---------------- host launcher ----------------
extern "C" void kernel_launch(void* const* d_in, const int* in_sizes, int n_in,
                              void* d_out, int out_size) {
    const float* x  = (const float*)d_in[0];
    const void*  ei = d_in[1];
    const float* ew = (const float*)d_in[2];
    const float* W1 = (const float*)d_in[3];
    const float* b1 = (const float*)d_in[4];
    const float* W2 = (const float*)d_in[5];
    const float* b2 = (const float*)d_in[6];
    const float* W3 = (const float*)d_in[7];
    const float* b3 = (const float*)d_in[8];

    const int n = in_sizes[0] / KDIM;   // 50000
    const int E = in_sizes[2];          // 1600000
    float* outp = (float*)d_out;

    const int TB = 256;
    const int nb_nodes = (n + TB - 1) / TB;
    const int nb_edges = (E + TB - 1) / TB;
    const int nchunk   = (n + 511) / 512;
    const int nprep    = (n * 16 + 5120 + TB - 1) / TB;
    const int gemm_blocks = (n + 63) / 64;
    const int gat_blocks  = (n * 32 + TB - 1) / TB;

    // ---- fork: side stream runs prep + GEMM1 concurrently with CSR build ----
    cudaStream_t s1;
    cudaStreamCreateWithFlags(&s1, cudaStreamNonBlocking);
    cudaEvent_t e0, e1;
    cudaEventCreateWithFlags(&e0, cudaEventDisableTiming);
    cudaEventCreateWithFlags(&e1, cudaEventDisableTiming);

    cudaEventRecord(e0, 0);
    cudaStreamWaitEvent(s1, e0, 0);

    // branch B (s1): fp16 conversion + layer-1 GEMM (depends only on x, W)
    k_prep<<<nprep, TB, 0, s1>>>((const float4*)x, (const float4*)W1,
                                 (const float4*)W2, (const float4*)W3, n);
    k_hgemm<128><<<gemm_blocks, 256, 0, s1>>>(0, n);

    // branch A (capture stream): CSR build
    k_init<<<nb_nodes, TB>>>(ei, n);
    k_edge_deg<<<nb_edges, TB>>>(ei, ew, E, n);
    k_scan_reduce<<<nchunk, 512>>>(n);
    k_scan_chunks<<<nchunk, 512>>>(n);
    k_edge_fill<<<nb_edges, TB>>>(ei, ew, E);

    // join
    cudaEventRecord(e1, s1);
    cudaStreamWaitEvent(0, e1, 0);

    // ---- layer 1 gather ----
    k_gather_h<<<gat_blocks, TB>>>(b1, n);

    // ---- layer 2 ----
    k_hgemm<128><<<gemm_blocks, 256>>>(2048, n);
    k_gather_h<<<gat_blocks, TB>>>(b2, n);

    // ---- layer 3 (fp16 h, fp32 out) ----
    k_hgemm<64><<<gemm_blocks, 256>>>(4096, n);
    k_gather_h64<<<gat_blocks, TB>>>(b3, outp, n);

    cudaEventDestroy(e0);
    cudaEventDestroy(e1);
    cudaStreamDestroy(s1);
}

// round 8
// speedup vs baseline: 1.0560x; 1.0560x over previous
#include <cuda_runtime.h>
#include <cuda_fp16.h>
#include <mma.h>
using namespace nvcuda;

// ---------------- problem constants ----------------
#define NMAX 50000
#define EMAX 1600000
#define KDIM 128

// ---------------- device scratch ----------------
__device__ unsigned long long g_degc[NMAX];  // bits 44+: cnt, bits 0..43: ew-sum in 2^-32 fixed point
__device__ float  g_dinv[NMAX];
__device__ int    g_cnt [NMAX];
__device__ int    g_off [NMAX];
__device__ int    g_rank[EMAX];              // within-bucket rank of each edge
__device__ int2   g_csr [EMAX];              // (src, norm-as-bits), bucketed by dst
__device__ int    g_bsum[256];
__device__ int    g_is64;
__device__ uint4  g_a16 [NMAX * KDIM / 8];   // fp16 activations (GEMM input)
__device__ uint4  g_hh  [NMAX * KDIM / 8];   // fp16 GEMM output (gather input)
__device__ uint4  g_w16 [5120];              // fp16 W1(2048) W2(2048) W3(1024) uint4s

// ---------------- fused init + dtype detect ----------------
__global__ void k_init(const void* __restrict__ ei, int n) {
    int i = blockIdx.x * blockDim.x + threadIdx.x;
    if (i < n) g_degc[i] = 0ULL;
    if (i == 0) {
        const long long* p = (const long long*)ei;
        int ok = 1;
#pragma unroll
        for (int t = 0; t < 16; t++) {
            long long v = p[t];
            if (v < 0 || v >= (long long)n) ok = 0;
        }
        g_is64 = ok;
    }
}

// ---------------- fp32 -> fp16 conversion: x and all weights ----------------
__device__ inline uint4 pack8(float4 a, float4 b) {
    __half2 h0 = __floats2half2_rn(a.x, a.y), h1 = __floats2half2_rn(a.z, a.w);
    __half2 h2 = __floats2half2_rn(b.x, b.y), h3 = __floats2half2_rn(b.z, b.w);
    uint4 u;
    u.x = *(unsigned*)&h0; u.y = *(unsigned*)&h1;
    u.z = *(unsigned*)&h2; u.w = *(unsigned*)&h3;
    return u;
}

__global__ void k_prep(const float4* __restrict__ x,
                       const float4* __restrict__ W1,
                       const float4* __restrict__ W2,
                       const float4* __restrict__ W3, int n) {
    int i = blockIdx.x * blockDim.x + threadIdx.x;
    int nx = n * 16;
    if (i < nx) {
        g_a16[i] = pack8(x[2 * i], x[2 * i + 1]);
    } else {
        int j = i - nx;
        if (j < 5120) {
            const float4* src; int jj;
            if (j < 2048)      { src = W1; jj = j; }
            else if (j < 4096) { src = W2; jj = j - 2048; }
            else               { src = W3; jj = j - 4096; }
            g_w16[j] = pack8(src[2 * jj], src[2 * jj + 1]);
        }
    }
}

// ---------------- edge pass 1: single packed atomic -> deg sum + count + rank ----------------
__global__ void k_edge_deg(const void* __restrict__ ei,
                           const float* __restrict__ ew, int E, int n) {
    int e = blockIdx.x * blockDim.x + threadIdx.x;
    if (e >= E) return;
    int s, d;
    if (g_is64) {
        const long long* p = (const long long*)ei;
        s = (int)p[e]; d = (int)p[E + e];
    } else {
        const int* p = (const int*)ei;
        s = p[e]; d = p[E + e];
    }
    if ((unsigned)s >= (unsigned)n || (unsigned)d >= (unsigned)n) { g_rank[e] = -1; return; }
    unsigned long long fx = (unsigned long long)((double)ew[e] * 4294967296.0);
    unsigned long long inc = (1ULL << 44) | fx;
    unsigned long long old = atomicAdd(&g_degc[d], inc);
    g_rank[e] = (int)(old >> 44);
}

// ---------------- scan reduce (+ fused dinv/cnt decode) ----------------
__global__ void k_scan_reduce(int n) {
    __shared__ int s[512];
    int t = threadIdx.x, i = blockIdx.x * 512 + t;
    int c = 0;
    if (i < n) {
        unsigned long long v = g_degc[i];
        float wsum = (float)((double)(v & ((1ULL << 44) - 1)) * (1.0 / 4294967296.0));
        g_dinv[i] = rsqrtf(wsum + 1.0f);          // +1 self-loop weight
        c = (int)(v >> 44);
        g_cnt[i] = c;
    }
    s[t] = c;
    __syncthreads();
    for (int st = 256; st > 0; st >>= 1) {
        if (t < st) s[t] += s[t + st];
        __syncthreads();
    }
    if (t == 0) g_bsum[blockIdx.x] = s[0];
}

// scan within chunk + inline prefix over preceding chunk sums
__global__ void k_scan_chunks(int n) {
    __shared__ int s[512];
    __shared__ int base;
    int t = threadIdx.x, i = blockIdx.x * 512 + t;
    if (t == 0) base = 0;
    __syncthreads();
    int partial = 0;
    for (int j = t; j < blockIdx.x; j += 512) partial += g_bsum[j];
    if (partial) atomicAdd(&base, partial);
    int v = (i < n) ? g_cnt[i] : 0;
    s[t] = v;
    __syncthreads();
    for (int st = 1; st < 512; st <<= 1) {
        int add = (t >= st) ? s[t - st] : 0;
        __syncthreads();
        s[t] += add;
        __syncthreads();
    }
    if (i < n) g_off[i] = s[t] - v + base;
}

// ---------------- edge pass 2: fill CSR (no atomics) ----------------
__global__ void k_edge_fill(const void* __restrict__ ei,
                            const float* __restrict__ ew, int E) {
    int e = blockIdx.x * blockDim.x + threadIdx.x;
    if (e >= E) return;
    int r = g_rank[e];
    if (r < 0) return;
    int s, d;
    if (g_is64) {
        const long long* p = (const long long*)ei;
        s = (int)p[e]; d = (int)p[E + e];
    } else {
        const int* p = (const int*)ei;
        s = p[e]; d = p[E + e];
    }
    float nrm = g_dinv[s] * ew[e] * g_dinv[d];
    g_csr[g_off[d] + r] = make_int2(s, __float_as_int(nrm));
}

// ---------------- tensor-core GEMM: C[M,N] = A16[M,128] @ W16[128,N] ----------------
template<int N>
__global__ void __launch_bounds__(256)
k_hgemm(int woff_u4, int M) {
    constexpr int BM  = 64;
    constexpr int LDA = 136;
    constexpr int WN  = N / 2;
    constexpr int NT  = WN / 16;
    constexpr int ABYTES = BM * LDA * 2;
    constexpr int SBYTES = 8 * 16 * WN * 4;
    __shared__ __align__(16) char sraw[(ABYTES > SBYTES) ? ABYTES : SBYTES];
    __half (*As)[LDA] = (__half(*)[LDA])sraw;
    float*  stage     = (float*)sraw;

    const __half* Wg = (const __half*)g_w16 + (long)woff_u4 * 8;

    const int tid  = threadIdx.x;
    const int wid  = tid >> 5, lane = tid & 31;
    const int wrow = wid >> 1, wcol = wid & 1;
    const int rb   = blockIdx.x * BM;

    for (int i = tid; i < BM * 16; i += 256) {
        int r = i >> 4, c = i & 15;
        uint4 v = make_uint4(0u, 0u, 0u, 0u);
        if (rb + r < M) v = g_a16[(long)(rb + r) * 16 + c];
        *(uint4*)&As[r][c * 8] = v;
    }
    __syncthreads();

    wmma::fragment<wmma::accumulator, 16, 16, 16, float> acc[NT];
#pragma unroll
    for (int j = 0; j < NT; j++) wmma::fill_fragment(acc[j], 0.0f);

    wmma::fragment<wmma::matrix_a, 16, 16, 16, __half, wmma::row_major> af;
    wmma::fragment<wmma::matrix_b, 16, 16, 16, __half, wmma::row_major> bf;
#pragma unroll
    for (int k = 0; k < 8; k++) {
        wmma::load_matrix_sync(af, &As[wrow * 16][k * 16], LDA);
#pragma unroll
        for (int j = 0; j < NT; j++) {
            wmma::load_matrix_sync(bf, Wg + (long)(k * 16) * N + wcol * WN + j * 16, N);
            wmma::mma_sync(acc[j], af, bf, acc[j]);
        }
    }
    __syncthreads();

    float* st = stage + wid * 16 * WN;
#pragma unroll
    for (int j = 0; j < NT; j++)
        wmma::store_matrix_sync(st + j * 16, acc[j], WN, wmma::mem_row_major);
    __syncwarp();

    const int r0 = rb + wrow * 16;
    unsigned* outh = (unsigned*)g_hh;
    for (int i = lane; i < 16 * WN / 2; i += 32) {
        int r = (i * 2) / WN, c = (i * 2) % WN;
        int gr = r0 + r;
        if (gr < M) {
            __half2 h = __floats2half2_rn(st[r * WN + c], st[r * WN + c + 1]);
            outh[((long)gr * N + wcol * WN + c) >> 1] = *(unsigned*)&h;
        }
    }
}

// ---------------- sparse aggregation, fp16 features, F=128 ----------------
__global__ void k_gather_h(const float* __restrict__ bias, int n) {
    const int gt   = blockIdx.x * blockDim.x + threadIdx.x;
    const int node = gt >> 5;
    const int lane = gt & 31;
    if (node >= n) return;

    const uint2* hh = (const uint2*)g_hh;

    float di = g_dinv[node];
    float sl = di * di;

    uint2 selfv = hh[(long)node * 32 + lane];
    __half2 s0 = *(__half2*)&selfv.x, s1 = *(__half2*)&selfv.y;
    float2 f0 = __half22float2(s0), f1 = __half22float2(s1);
    float ax = f0.x * sl, ay = f0.y * sl, az = f1.x * sl, aw = f1.y * sl;

    const int o = g_off[node];
    const int c = g_cnt[node];
#pragma unroll 4
    for (int k = 0; k < c; k++) {
        int2 sp = g_csr[o + k];
        float nrm = __int_as_float(sp.y);
        uint2 hv = hh[(long)sp.x * 32 + lane];
        __half2 h0 = *(__half2*)&hv.x, h1 = *(__half2*)&hv.y;
        float2 g0 = __half22float2(h0), g1 = __half22float2(h1);
        ax = fmaf(g0.x, nrm, ax);
        ay = fmaf(g0.y, nrm, ay);
        az = fmaf(g1.x, nrm, az);
        aw = fmaf(g1.y, nrm, aw);
    }
    float4 bv = *(const float4*)(bias + lane * 4);
    float rx = fmaxf(ax + bv.x, 0.f);
    float ry = fmaxf(ay + bv.y, 0.f);
    float rz = fmaxf(az + bv.z, 0.f);
    float rw = fmaxf(aw + bv.w, 0.f);
    __half2 o0 = __floats2half2_rn(rx, ry), o1 = __floats2half2_rn(rz, rw);
    uint2 u; u.x = *(unsigned*)&o0; u.y = *(unsigned*)&o1;
    ((uint2*)g_a16)[(long)node * 32 + lane] = u;
}

// ---------------- sparse aggregation, fp16, F=64 (final, fp32 out) ----------------
__global__ void k_gather_h64(const float* __restrict__ bias,
                             float* __restrict__ outp, int n) {
    const int gt   = blockIdx.x * blockDim.x + threadIdx.x;
    const int node = gt >> 5;
    const int lane = gt & 31;
    if (node >= n) return;

    const unsigned* hh = (const unsigned*)g_hh;   // half2 units, 32 per node

    float di = g_dinv[node];
    float sl = di * di;

    unsigned selfv = hh[(long)node * 32 + lane];
    float2 f = __half22float2(*(__half2*)&selfv);
    float ax = f.x * sl, ay = f.y * sl;

    const int o = g_off[node];
    const int c = g_cnt[node];
#pragma unroll 4
    for (int k = 0; k < c; k++) {
        int2 sp = g_csr[o + k];
        float nrm = __int_as_float(sp.y);
        unsigned hv = hh[(long)sp.x * 32 + lane];
        float2 g = __half22float2(*(__half2*)&hv);
        ax = fmaf(g.x, nrm, ax);
        ay = fmaf(g.y, nrm, ay);
    }
    float2 bv = *(const float2*)(bias + lane * 2);
    *(float2*)(outp + (long)node * 64 + lane * 2) = make_float2(ax + bv.x, ay + bv.y);
}

// ---------------- host launcher ----------------
extern "C" void kernel_launch(void* const* d_in, const int* in_sizes, int n_in,
                              void* d_out, int out_size) {
    const float* x  = (const float*)d_in[0];
    const void*  ei = d_in[1];
    const float* ew = (const float*)d_in[2];
    const float* W1 = (const float*)d_in[3];
    const float* b1 = (const float*)d_in[4];
    const float* W2 = (const float*)d_in[5];
    const float* b2 = (const float*)d_in[6];
    const float* W3 = (const float*)d_in[7];
    const float* b3 = (const float*)d_in[8];

    const int n = in_sizes[0] / KDIM;   // 50000
    const int E = in_sizes[2];          // 1600000
    float* outp = (float*)d_out;

    const int TB = 256;
    const int nb_nodes = (n + TB - 1) / TB;
    const int nb_edges = (E + TB - 1) / TB;
    const int nchunk   = (n + 511) / 512;
    const int nprep    = (n * 16 + 5120 + TB - 1) / TB;
    const int gemm_blocks = (n + 63) / 64;
    const int gat_blocks  = (n * 32 + TB - 1) / TB;

    // ---- fork: side stream runs prep + GEMM1 concurrently with CSR build ----
    cudaStream_t s1;
    cudaStreamCreateWithFlags(&s1, cudaStreamNonBlocking);
    cudaEvent_t e0, e1;
    cudaEventCreateWithFlags(&e0, cudaEventDisableTiming);
    cudaEventCreateWithFlags(&e1, cudaEventDisableTiming);

    cudaEventRecord(e0, 0);
    cudaStreamWaitEvent(s1, e0, 0);

    // branch B (s1): fp16 conversion + layer-1 GEMM (depends only on x, W)
    k_prep<<<nprep, TB, 0, s1>>>((const float4*)x, (const float4*)W1,
                                 (const float4*)W2, (const float4*)W3, n);
    k_hgemm<128><<<gemm_blocks, 256, 0, s1>>>(0, n);

    // branch A (capture stream): CSR build
    k_init<<<nb_nodes, TB>>>(ei, n);
    k_edge_deg<<<nb_edges, TB>>>(ei, ew, E, n);
    k_scan_reduce<<<nchunk, 512>>>(n);
    k_scan_chunks<<<nchunk, 512>>>(n);
    k_edge_fill<<<nb_edges, TB>>>(ei, ew, E);

    // join
    cudaEventRecord(e1, s1);
    cudaStreamWaitEvent(0, e1, 0);

    // ---- layer 1 gather ----
    k_gather_h<<<gat_blocks, TB>>>(b1, n);

    // ---- layer 2 ----
    k_hgemm<128><<<gemm_blocks, 256>>>(2048, n);
    k_gather_h<<<gat_blocks, TB>>>(b2, n);

    // ---- layer 3 (fp16 h, fp32 out) ----
    k_hgemm<64><<<gemm_blocks, 256>>>(4096, n);
    k_gather_h64<<<gat_blocks, TB>>>(b3, outp, n);

    cudaEventDestroy(e0);
    cudaEventDestroy(e1);
    cudaStreamDestroy(s1);
}

// round 9
// speedup vs baseline: 1.1161x; 1.0569x over previous
#include <cuda_runtime.h>
#include <cuda_fp16.h>
#include <mma.h>
using namespace nvcuda;

// ---------------- problem constants ----------------
#define NMAX 50000
#define EMAX 1600000
#define KDIM 128

// ---------------- device scratch ----------------
__device__ unsigned long long g_degc[NMAX];  // bits 44+: cnt, bits 0..43: ew-sum (2^-32 fixed)
__device__ float  g_dinv[NMAX];
__device__ int    g_cnt [NMAX];
__device__ int    g_off [NMAX];
__device__ int    g_rank[EMAX];
__device__ int2   g_csr [EMAX];              // (src, norm-as-bits), bucketed by dst
__device__ int    g_bsum[256];
__device__ int    g_is64;
__device__ uint4  g_a16 [NMAX * KDIM / 8];   // fp16 activations (GEMM input)
__device__ uint4  g_hh  [NMAX * KDIM / 8];   // fp16 GEMM output (gather input)
__device__ uint4  g_w16 [5120];              // fp16 W1(2048) W2(2048) W3(1024)

// ---------------- fused init + dtype detect ----------------
__global__ void k_init(const void* __restrict__ ei, int n) {
    int i = blockIdx.x * blockDim.x + threadIdx.x;
    if (i < n) g_degc[i] = 0ULL;
    if (i == 0) {
        const long long* p = (const long long*)ei;
        int ok = 1;
#pragma unroll
        for (int t = 0; t < 16; t++) {
            long long v = p[t];
            if (v < 0 || v >= (long long)n) ok = 0;
        }
        g_is64 = ok;
    }
}

// ---------------- fp32 -> fp16 conversion ----------------
__device__ inline uint4 pack8(float4 a, float4 b) {
    __half2 h0 = __floats2half2_rn(a.x, a.y), h1 = __floats2half2_rn(a.z, a.w);
    __half2 h2 = __floats2half2_rn(b.x, b.y), h3 = __floats2half2_rn(b.z, b.w);
    uint4 u;
    u.x = *(unsigned*)&h0; u.y = *(unsigned*)&h1;
    u.z = *(unsigned*)&h2; u.w = *(unsigned*)&h3;
    return u;
}

__global__ void k_prep(const float4* __restrict__ x,
                       const float4* __restrict__ W1,
                       const float4* __restrict__ W2,
                       const float4* __restrict__ W3, int n) {
    int i = blockIdx.x * blockDim.x + threadIdx.x;
    int nx = n * 16;
    if (i < nx) {
        g_a16[i] = pack8(x[2 * i], x[2 * i + 1]);
    } else {
        int j = i - nx;
        if (j < 5120) {
            const float4* src; int jj;
            if (j < 2048)      { src = W1; jj = j; }
            else if (j < 4096) { src = W2; jj = j - 2048; }
            else               { src = W3; jj = j - 4096; }
            g_w16[j] = pack8(src[2 * jj], src[2 * jj + 1]);
        }
    }
}

// ---------------- edge pass 1: single packed atomic ----------------
__global__ void k_edge_deg(const void* __restrict__ ei,
                           const float* __restrict__ ew, int E, int n) {
    int e = blockIdx.x * blockDim.x + threadIdx.x;
    if (e >= E) return;
    int s, d;
    if (g_is64) {
        const long long* p = (const long long*)ei;
        s = (int)p[e]; d = (int)p[E + e];
    } else {
        const int* p = (const int*)ei;
        s = p[e]; d = p[E + e];
    }
    if ((unsigned)s >= (unsigned)n || (unsigned)d >= (unsigned)n) { g_rank[e] = -1; return; }
    unsigned long long fx = (unsigned long long)((double)ew[e] * 4294967296.0);
    unsigned long long inc = (1ULL << 44) | fx;
    unsigned long long old = atomicAdd(&g_degc[d], inc);
    g_rank[e] = (int)(old >> 44);
}

// ---------------- scan reduce (+ fused dinv/cnt decode) ----------------
__global__ void k_scan_reduce(int n) {
    __shared__ int s[512];
    int t = threadIdx.x, i = blockIdx.x * 512 + t;
    int c = 0;
    if (i < n) {
        unsigned long long v = g_degc[i];
        float wsum = (float)((double)(v & ((1ULL << 44) - 1)) * (1.0 / 4294967296.0));
        g_dinv[i] = rsqrtf(wsum + 1.0f);
        c = (int)(v >> 44);
        g_cnt[i] = c;
    }
    s[t] = c;
    __syncthreads();
    for (int st = 256; st > 0; st >>= 1) {
        if (t < st) s[t] += s[t + st];
        __syncthreads();
    }
    if (t == 0) g_bsum[blockIdx.x] = s[0];
}

__global__ void k_scan_chunks(int n) {
    __shared__ int s[512];
    __shared__ int base;
    int t = threadIdx.x, i = blockIdx.x * 512 + t;
    if (t == 0) base = 0;
    __syncthreads();
    int partial = 0;
    for (int j = t; j < blockIdx.x; j += 512) partial += g_bsum[j];
    if (partial) atomicAdd(&base, partial);
    int v = (i < n) ? g_cnt[i] : 0;
    s[t] = v;
    __syncthreads();
    for (int st = 1; st < 512; st <<= 1) {
        int add = (t >= st) ? s[t - st] : 0;
        __syncthreads();
        s[t] += add;
        __syncthreads();
    }
    if (i < n) g_off[i] = s[t] - v + base;
}

// ---------------- edge pass 2: fill CSR (no atomics) ----------------
__global__ void k_edge_fill(const void* __restrict__ ei,
                            const float* __restrict__ ew, int E) {
    int e = blockIdx.x * blockDim.x + threadIdx.x;
    if (e >= E) return;
    int r = g_rank[e];
    if (r < 0) return;
    int s, d;
    if (g_is64) {
        const long long* p = (const long long*)ei;
        s = (int)p[e]; d = (int)p[E + e];
    } else {
        const int* p = (const int*)ei;
        s = p[e]; d = p[E + e];
    }
    float nrm = g_dinv[s] * ew[e] * g_dinv[d];
    g_csr[g_off[d] + r] = make_int2(s, __float_as_int(nrm));
}

// ---------------- tensor-core GEMM: C[M,N] = A16[M,128] @ W16[128,N] ----------------
template<int N>
__global__ void __launch_bounds__(256)
k_hgemm(int woff_u4, int M) {
    constexpr int BM  = 64;
    constexpr int LDA = 136;
    constexpr int WN  = N / 2;
    constexpr int NT  = WN / 16;
    constexpr int ABYTES = BM * LDA * 2;
    constexpr int SBYTES = 8 * 16 * WN * 4;
    __shared__ __align__(16) char sraw[(ABYTES > SBYTES) ? ABYTES : SBYTES];
    __half (*As)[LDA] = (__half(*)[LDA])sraw;
    float*  stage     = (float*)sraw;

    const __half* Wg = (const __half*)g_w16 + (long)woff_u4 * 8;

    const int tid  = threadIdx.x;
    const int wid  = tid >> 5, lane = tid & 31;
    const int wrow = wid >> 1, wcol = wid & 1;
    const int rb   = blockIdx.x * BM;

    for (int i = tid; i < BM * 16; i += 256) {
        int r = i >> 4, c = i & 15;
        uint4 v = make_uint4(0u, 0u, 0u, 0u);
        if (rb + r < M) v = g_a16[(long)(rb + r) * 16 + c];
        *(uint4*)&As[r][c * 8] = v;
    }
    __syncthreads();

    wmma::fragment<wmma::accumulator, 16, 16, 16, float> acc[NT];
#pragma unroll
    for (int j = 0; j < NT; j++) wmma::fill_fragment(acc[j], 0.0f);

    wmma::fragment<wmma::matrix_a, 16, 16, 16, __half, wmma::row_major> af;
    wmma::fragment<wmma::matrix_b, 16, 16, 16, __half, wmma::row_major> bf;
#pragma unroll
    for (int k = 0; k < 8; k++) {
        wmma::load_matrix_sync(af, &As[wrow * 16][k * 16], LDA);
#pragma unroll
        for (int j = 0; j < NT; j++) {
            wmma::load_matrix_sync(bf, Wg + (long)(k * 16) * N + wcol * WN + j * 16, N);
            wmma::mma_sync(acc[j], af, bf, acc[j]);
        }
    }
    __syncthreads();

    float* st = stage + wid * 16 * WN;
#pragma unroll
    for (int j = 0; j < NT; j++)
        wmma::store_matrix_sync(st + j * 16, acc[j], WN, wmma::mem_row_major);
    __syncwarp();

    const int r0 = rb + wrow * 16;
    unsigned* outh = (unsigned*)g_hh;
    for (int i = lane; i < 16 * WN / 2; i += 32) {
        int r = (i * 2) / WN, c = (i * 2) % WN;
        int gr = r0 + r;
        if (gr < M) {
            __half2 h = __floats2half2_rn(st[r * WN + c], st[r * WN + c + 1]);
            outh[((long)gr * N + wcol * WN + c) >> 1] = *(unsigned*)&h;
        }
    }
}

// ---------------- helpers for fp16 row math ----------------
__device__ inline void fma8(const uint4& hv, float nrm, float* a) {
    __half2 h0 = *(__half2*)&hv.x, h1 = *(__half2*)&hv.y;
    __half2 h2 = *(__half2*)&hv.z, h3 = *(__half2*)&hv.w;
    float2 f0 = __half22float2(h0), f1 = __half22float2(h1);
    float2 f2 = __half22float2(h2), f3 = __half22float2(h3);
    a[0] = fmaf(f0.x, nrm, a[0]); a[1] = fmaf(f0.y, nrm, a[1]);
    a[2] = fmaf(f1.x, nrm, a[2]); a[3] = fmaf(f1.y, nrm, a[3]);
    a[4] = fmaf(f2.x, nrm, a[4]); a[5] = fmaf(f2.y, nrm, a[5]);
    a[6] = fmaf(f3.x, nrm, a[6]); a[7] = fmaf(f3.y, nrm, a[7]);
}

// ---------------- sparse aggregation, fp16, F=128: half-warp per node ----------------
// 16 lanes x uint4 = 256B row per half-warp; 2 independent edge streams per warp.
__global__ void __launch_bounds__(256) k_gather_h(const float* __restrict__ bias, int n) {
    const int gt   = blockIdx.x * blockDim.x + threadIdx.x;
    const int node = gt >> 4;
    const int sub  = gt & 15;            // lane owns features 8*sub .. 8*sub+7
    if (node >= n) return;

    float di = g_dinv[node];
    float sl = di * di;

    float a[8];
    {
        uint4 sv = g_hh[(long)node * 16 + sub];
        __half2 h0 = *(__half2*)&sv.x, h1 = *(__half2*)&sv.y;
        __half2 h2 = *(__half2*)&sv.z, h3 = *(__half2*)&sv.w;
        float2 f0 = __half22float2(h0), f1 = __half22float2(h1);
        float2 f2 = __half22float2(h2), f3 = __half22float2(h3);
        a[0] = f0.x * sl; a[1] = f0.y * sl; a[2] = f1.x * sl; a[3] = f1.y * sl;
        a[4] = f2.x * sl; a[5] = f2.y * sl; a[6] = f3.x * sl; a[7] = f3.y * sl;
    }

    const int o = g_off[node];
    const int c = g_cnt[node];
#pragma unroll 4
    for (int k = 0; k < c; k++) {
        int2 sp = g_csr[o + k];                       // broadcast within half-warp
        float nrm = __int_as_float(sp.y);
        uint4 hv = g_hh[(long)sp.x * 16 + sub];       // 256B per half-warp
        fma8(hv, nrm, a);
    }

    float4 b0 = *(const float4*)(bias + sub * 8);
    float4 b1 = *(const float4*)(bias + sub * 8 + 4);
    float r0 = fmaxf(a[0] + b0.x, 0.f), r1 = fmaxf(a[1] + b0.y, 0.f);
    float r2 = fmaxf(a[2] + b0.z, 0.f), r3 = fmaxf(a[3] + b0.w, 0.f);
    float r4 = fmaxf(a[4] + b1.x, 0.f), r5 = fmaxf(a[5] + b1.y, 0.f);
    float r6 = fmaxf(a[6] + b1.z, 0.f), r7 = fmaxf(a[7] + b1.w, 0.f);
    __half2 p0 = __floats2half2_rn(r0, r1), p1 = __floats2half2_rn(r2, r3);
    __half2 p2 = __floats2half2_rn(r4, r5), p3 = __floats2half2_rn(r6, r7);
    uint4 u;
    u.x = *(unsigned*)&p0; u.y = *(unsigned*)&p1;
    u.z = *(unsigned*)&p2; u.w = *(unsigned*)&p3;
    g_a16[(long)node * 16 + sub] = u;
}

// ---------------- sparse aggregation, fp16, F=64 (final, fp32 out): 8 lanes/node ----------------
__global__ void __launch_bounds__(256) k_gather_h64(const float* __restrict__ bias,
                                                    float* __restrict__ outp, int n) {
    const int gt   = blockIdx.x * blockDim.x + threadIdx.x;
    const int node = gt >> 3;
    const int sub  = gt & 7;             // lane owns features 8*sub .. 8*sub+7
    if (node >= n) return;

    float di = g_dinv[node];
    float sl = di * di;

    float a[8];
    {
        uint4 sv = g_hh[(long)node * 8 + sub];
        __half2 h0 = *(__half2*)&sv.x, h1 = *(__half2*)&sv.y;
        __half2 h2 = *(__half2*)&sv.z, h3 = *(__half2*)&sv.w;
        float2 f0 = __half22float2(h0), f1 = __half22float2(h1);
        float2 f2 = __half22float2(h2), f3 = __half22float2(h3);
        a[0] = f0.x * sl; a[1] = f0.y * sl; a[2] = f1.x * sl; a[3] = f1.y * sl;
        a[4] = f2.x * sl; a[5] = f2.y * sl; a[6] = f3.x * sl; a[7] = f3.y * sl;
    }

    const int o = g_off[node];
    const int c = g_cnt[node];
#pragma unroll 4
    for (int k = 0; k < c; k++) {
        int2 sp = g_csr[o + k];
        float nrm = __int_as_float(sp.y);
        uint4 hv = g_hh[(long)sp.x * 8 + sub];
        fma8(hv, nrm, a);
    }

    float4 b0 = *(const float4*)(bias + sub * 8);
    float4 b1 = *(const float4*)(bias + sub * 8 + 4);
    float4 o0 = make_float4(a[0] + b0.x, a[1] + b0.y, a[2] + b0.z, a[3] + b0.w);
    float4 o1 = make_float4(a[4] + b1.x, a[5] + b1.y, a[6] + b1.z, a[7] + b1.w);
    *(float4*)(outp + (long)node * 64 + sub * 8)     = o0;
    *(float4*)(outp + (long)node * 64 + sub * 8 + 4) = o1;
}

// ---------------- host launcher ----------------
extern "C" void kernel_launch(void* const* d_in, const int* in_sizes, int n_in,
                              void* d_out, int out_size) {
    const float* x  = (const float*)d_in[0];
    const void*  ei = d_in[1];
    const float* ew = (const float*)d_in[2];
    const float* W1 = (const float*)d_in[3];
    const float* b1 = (const float*)d_in[4];
    const float* W2 = (const float*)d_in[5];
    const float* b2 = (const float*)d_in[6];
    const float* W3 = (const float*)d_in[7];
    const float* b3 = (const float*)d_in[8];

    const int n = in_sizes[0] / KDIM;   // 50000
    const int E = in_sizes[2];          // 1600000
    float* outp = (float*)d_out;

    const int TB = 256;
    const int nb_nodes = (n + TB - 1) / TB;
    const int nb_edges = (E + TB - 1) / TB;
    const int nchunk   = (n + 511) / 512;
    const int nprep    = (n * 16 + 5120 + TB - 1) / TB;
    const int gemm_blocks = (n + 63) / 64;
    const int gat128_blocks = (n * 16 + TB - 1) / TB;
    const int gat64_blocks  = (n * 8 + TB - 1) / TB;

    // ---- fork: side stream runs prep + GEMM1 concurrently with CSR build ----
    cudaStream_t s1;
    cudaStreamCreateWithFlags(&s1, cudaStreamNonBlocking);
    cudaEvent_t e0, e1;
    cudaEventCreateWithFlags(&e0, cudaEventDisableTiming);
    cudaEventCreateWithFlags(&e1, cudaEventDisableTiming);

    cudaEventRecord(e0, 0);
    cudaStreamWaitEvent(s1, e0, 0);

    k_prep<<<nprep, TB, 0, s1>>>((const float4*)x, (const float4*)W1,
                                 (const float4*)W2, (const float4*)W3, n);
    k_hgemm<128><<<gemm_blocks, 256, 0, s1>>>(0, n);

    k_init<<<nb_nodes, TB>>>(ei, n);
    k_edge_deg<<<nb_edges, TB>>>(ei, ew, E, n);
    k_scan_reduce<<<nchunk, 512>>>(n);
    k_scan_chunks<<<nchunk, 512>>>(n);
    k_edge_fill<<<nb_edges, TB>>>(ei, ew, E);

    cudaEventRecord(e1, s1);
    cudaStreamWaitEvent(0, e1, 0);

    // ---- layer 1 gather ----
    k_gather_h<<<gat128_blocks, TB>>>(b1, n);

    // ---- layer 2 ----
    k_hgemm<128><<<gemm_blocks, 256>>>(2048, n);
    k_gather_h<<<gat128_blocks, TB>>>(b2, n);

    // ---- layer 3 ----
    k_hgemm<64><<<gemm_blocks, 256>>>(4096, n);
    k_gather_h64<<<gat64_blocks, TB>>>(b3, outp, n);

    cudaEventDestroy(e0);
    cudaEventDestroy(e1);
    cudaStreamDestroy(s1);
}

// round 10
// speedup vs baseline: 1.1240x; 1.0071x over previous
#include <cuda_runtime.h>
#include <cuda_fp16.h>
#include <mma.h>
using namespace nvcuda;

// ---------------- problem constants ----------------
#define NMAX 50000
#define EMAX 1600000
#define KDIM 128

// ---------------- device scratch ----------------
__device__ unsigned long long g_degc[NMAX];  // bits 44+: cnt, bits 0..43: ew-sum (2^-32 fixed)
__device__ float  g_dinv[NMAX];
__device__ int    g_cnt [NMAX];
__device__ int    g_off [NMAX];
__device__ int    g_rank[EMAX];
__device__ int2   g_csr [EMAX];              // (src, norm-as-bits), bucketed by dst
__device__ unsigned g_agg[256];              // lookback state: bit31 flag | aggregate
__device__ int    g_is64;
__device__ uint4  g_a16 [NMAX * KDIM / 8];   // fp16 activations (GEMM input)
__device__ uint4  g_hh  [NMAX * KDIM / 8];   // fp16 GEMM output (gather input)
__device__ uint4  g_w16 [5120];              // fp16 W1(2048) W2(2048) W3(1024)

// ---------------- fused init + dtype detect ----------------
__global__ void k_init(const void* __restrict__ ei, int n) {
    int i = blockIdx.x * blockDim.x + threadIdx.x;
    if (i < n) g_degc[i] = 0ULL;
    if (i < 256) g_agg[i] = 0u;
    if (i == 0) {
        const long long* p = (const long long*)ei;
        int ok = 1;
#pragma unroll
        for (int t = 0; t < 16; t++) {
            long long v = p[t];
            if (v < 0 || v >= (long long)n) ok = 0;
        }
        g_is64 = ok;
    }
}

// ---------------- fp32 -> fp16 conversion ----------------
__device__ inline uint4 pack8(float4 a, float4 b) {
    __half2 h0 = __floats2half2_rn(a.x, a.y), h1 = __floats2half2_rn(a.z, a.w);
    __half2 h2 = __floats2half2_rn(b.x, b.y), h3 = __floats2half2_rn(b.z, b.w);
    uint4 u;
    u.x = *(unsigned*)&h0; u.y = *(unsigned*)&h1;
    u.z = *(unsigned*)&h2; u.w = *(unsigned*)&h3;
    return u;
}

__global__ void k_prep(const float4* __restrict__ x,
                       const float4* __restrict__ W1,
                       const float4* __restrict__ W2,
                       const float4* __restrict__ W3, int n) {
    int i = blockIdx.x * blockDim.x + threadIdx.x;
    int nx = n * 16;
    if (i < nx) {
        g_a16[i] = pack8(x[2 * i], x[2 * i + 1]);
    } else {
        int j = i - nx;
        if (j < 5120) {
            const float4* src; int jj;
            if (j < 2048)      { src = W1; jj = j; }
            else if (j < 4096) { src = W2; jj = j - 2048; }
            else               { src = W3; jj = j - 4096; }
            g_w16[j] = pack8(src[2 * jj], src[2 * jj + 1]);
        }
    }
}

// ---------------- edge pass 1: 2 edges/thread, single packed atomic each ----------------
__global__ void k_edge_deg(const void* __restrict__ ei,
                           const float* __restrict__ ew, int E, int n) {
    int e = (blockIdx.x * blockDim.x + threadIdx.x) * 2;
    if (e >= E) return;
    int s0, d0, s1 = -1, d1 = -1;
    bool two = (e + 1 < E);
    if (g_is64) {
        const long long* p = (const long long*)ei;
        s0 = (int)p[e]; d0 = (int)p[E + e];
        if (two) { s1 = (int)p[e + 1]; d1 = (int)p[E + e + 1]; }
    } else {
        const int* p = (const int*)ei;
        int2 sv = *(const int2*)(p + e);
        int2 dv = *(const int2*)(p + E + e);
        s0 = sv.x; d0 = dv.x;
        if (two) { s1 = sv.y; d1 = dv.y; }
    }
    float2 wv = two ? *(const float2*)(ew + e) : make_float2(ew[e], 0.f);
    int r0 = -1, r1 = -1;
    if ((unsigned)s0 < (unsigned)n && (unsigned)d0 < (unsigned)n) {
        unsigned long long fx = (unsigned long long)((double)wv.x * 4294967296.0);
        r0 = (int)(atomicAdd(&g_degc[d0], (1ULL << 44) | fx) >> 44);
    }
    if (two) {
        if ((unsigned)s1 < (unsigned)n && (unsigned)d1 < (unsigned)n) {
            unsigned long long fx = (unsigned long long)((double)wv.y * 4294967296.0);
            r1 = (int)(atomicAdd(&g_degc[d1], (1ULL << 44) | fx) >> 44);
        }
        *(int2*)(g_rank + e) = make_int2(r0, r1);
    } else {
        g_rank[e] = r0;
    }
}

// ---------------- single-kernel scan: decode degc -> dinv/cnt, lookback prefix -> off ----------------
// grid = ceil(n/512) (98 blocks, all resident) -- aggregate-only lookback, deadlock-free.
__global__ void k_scan(int n) {
    __shared__ int s[512];
    __shared__ int base;
    const int t = threadIdx.x, b = blockIdx.x, i = b * 512 + t;
    int c = 0;
    if (i < n) {
        unsigned long long v = g_degc[i];
        float wsum = (float)((double)(v & ((1ULL << 44) - 1)) * (1.0 / 4294967296.0));
        g_dinv[i] = rsqrtf(wsum + 1.0f);          // +1 self-loop weight
        c = (int)(v >> 44);
        g_cnt[i] = c;
    }
    s[t] = c;
    __syncthreads();
    // inclusive Hillis-Steele scan
    for (int st = 1; st < 512; st <<= 1) {
        int add = (t >= st) ? s[t - st] : 0;
        __syncthreads();
        s[t] += add;
        __syncthreads();
    }
    // publish this block's aggregate
    if (t == 511) atomicExch(&g_agg[b], 0x80000000u | (unsigned)s[511]);
    if (t == 0) base = 0;
    __syncthreads();
    // lookback: lane t polls predecessors t, t+512, ...
    int partial = 0;
    for (int j = t; j < b; j += 512) {
        unsigned v;
        do { v = atomicAdd(&g_agg[j], 0u); } while (!(v & 0x80000000u));
        partial += (int)(v & 0x7fffffffu);
    }
    if (partial) atomicAdd(&base, partial);
    __syncthreads();
    if (i < n) g_off[i] = base + s[t] - c;       // exclusive prefix
}

// ---------------- edge pass 2: 2 edges/thread, fill CSR (no atomics) ----------------
__global__ void k_edge_fill(const void* __restrict__ ei,
                            const float* __restrict__ ew, int E) {
    int e = (blockIdx.x * blockDim.x + threadIdx.x) * 2;
    if (e >= E) return;
    bool two = (e + 1 < E);
    int2 rr = two ? *(const int2*)(g_rank + e) : make_int2(g_rank[e], -1);
    int s0, d0, s1 = 0, d1 = 0;
    if (g_is64) {
        const long long* p = (const long long*)ei;
        s0 = (int)p[e]; d0 = (int)p[E + e];
        if (two) { s1 = (int)p[e + 1]; d1 = (int)p[E + e + 1]; }
    } else {
        const int* p = (const int*)ei;
        int2 sv = *(const int2*)(p + e);
        int2 dv = *(const int2*)(p + E + e);
        s0 = sv.x; d0 = dv.x; s1 = sv.y; d1 = dv.y;
    }
    float2 wv = two ? *(const float2*)(ew + e) : make_float2(ew[e], 0.f);
    if (rr.x >= 0) {
        float nrm = g_dinv[s0] * wv.x * g_dinv[d0];
        g_csr[g_off[d0] + rr.x] = make_int2(s0, __float_as_int(nrm));
    }
    if (two && rr.y >= 0) {
        float nrm = g_dinv[s1] * wv.y * g_dinv[d1];
        g_csr[g_off[d1] + rr.y] = make_int2(s1, __float_as_int(nrm));
    }
}

// ---------------- tensor-core GEMM: C[M,N] = A16[M,128] @ W16[128,N] ----------------
template<int N>
__global__ void __launch_bounds__(256)
k_hgemm(int woff_u4, int M) {
    constexpr int BM  = 64;
    constexpr int LDA = 136;
    constexpr int WN  = N / 2;
    constexpr int NT  = WN / 16;
    constexpr int ABYTES = BM * LDA * 2;
    constexpr int SBYTES = 8 * 16 * WN * 4;
    __shared__ __align__(16) char sraw[(ABYTES > SBYTES) ? ABYTES : SBYTES];
    __half (*As)[LDA] = (__half(*)[LDA])sraw;
    float*  stage     = (float*)sraw;

    const __half* Wg = (const __half*)g_w16 + (long)woff_u4 * 8;

    const int tid  = threadIdx.x;
    const int wid  = tid >> 5, lane = tid & 31;
    const int wrow = wid >> 1, wcol = wid & 1;
    const int rb   = blockIdx.x * BM;

    for (int i = tid; i < BM * 16; i += 256) {
        int r = i >> 4, c = i & 15;
        uint4 v = make_uint4(0u, 0u, 0u, 0u);
        if (rb + r < M) v = g_a16[(long)(rb + r) * 16 + c];
        *(uint4*)&As[r][c * 8] = v;
    }
    __syncthreads();

    wmma::fragment<wmma::accumulator, 16, 16, 16, float> acc[NT];
#pragma unroll
    for (int j = 0; j < NT; j++) wmma::fill_fragment(acc[j], 0.0f);

    wmma::fragment<wmma::matrix_a, 16, 16, 16, __half, wmma::row_major> af;
    wmma::fragment<wmma::matrix_b, 16, 16, 16, __half, wmma::row_major> bf;
#pragma unroll
    for (int k = 0; k < 8; k++) {
        wmma::load_matrix_sync(af, &As[wrow * 16][k * 16], LDA);
#pragma unroll
        for (int j = 0; j < NT; j++) {
            wmma::load_matrix_sync(bf, Wg + (long)(k * 16) * N + wcol * WN + j * 16, N);
            wmma::mma_sync(acc[j], af, bf, acc[j]);
        }
    }
    __syncthreads();

    float* st = stage + wid * 16 * WN;
#pragma unroll
    for (int j = 0; j < NT; j++)
        wmma::store_matrix_sync(st + j * 16, acc[j], WN, wmma::mem_row_major);
    __syncwarp();

    const int r0 = rb + wrow * 16;
    unsigned* outh = (unsigned*)g_hh;
    for (int i = lane; i < 16 * WN / 2; i += 32) {
        int r = (i * 2) / WN, c = (i * 2) % WN;
        int gr = r0 + r;
        if (gr < M) {
            __half2 h = __floats2half2_rn(st[r * WN + c], st[r * WN + c + 1]);
            outh[((long)gr * N + wcol * WN + c) >> 1] = *(unsigned*)&h;
        }
    }
}

// ---------------- helpers for fp16 row math ----------------
__device__ inline void fma8(const uint4& hv, float nrm, float* a) {
    __half2 h0 = *(__half2*)&hv.x, h1 = *(__half2*)&hv.y;
    __half2 h2 = *(__half2*)&hv.z, h3 = *(__half2*)&hv.w;
    float2 f0 = __half22float2(h0), f1 = __half22float2(h1);
    float2 f2 = __half22float2(h2), f3 = __half22float2(h3);
    a[0] = fmaf(f0.x, nrm, a[0]); a[1] = fmaf(f0.y, nrm, a[1]);
    a[2] = fmaf(f1.x, nrm, a[2]); a[3] = fmaf(f1.y, nrm, a[3]);
    a[4] = fmaf(f2.x, nrm, a[4]); a[5] = fmaf(f2.y, nrm, a[5]);
    a[6] = fmaf(f3.x, nrm, a[6]); a[7] = fmaf(f3.y, nrm, a[7]);
}

// ---------------- sparse aggregation, fp16, F=128: half-warp per node ----------------
__global__ void __launch_bounds__(256) k_gather_h(const float* __restrict__ bias, int n) {
    const int gt   = blockIdx.x * blockDim.x + threadIdx.x;
    const int node = gt >> 4;
    const int sub  = gt & 15;            // lane owns features 8*sub .. 8*sub+7
    if (node >= n) return;

    float di = g_dinv[node];
    float sl = di * di;

    float a[8];
    {
        uint4 sv = g_hh[(long)node * 16 + sub];
        __half2 h0 = *(__half2*)&sv.x, h1 = *(__half2*)&sv.y;
        __half2 h2 = *(__half2*)&sv.z, h3 = *(__half2*)&sv.w;
        float2 f0 = __half22float2(h0), f1 = __half22float2(h1);
        float2 f2 = __half22float2(h2), f3 = __half22float2(h3);
        a[0] = f0.x * sl; a[1] = f0.y * sl; a[2] = f1.x * sl; a[3] = f1.y * sl;
        a[4] = f2.x * sl; a[5] = f2.y * sl; a[6] = f3.x * sl; a[7] = f3.y * sl;
    }

    const int o = g_off[node];
    const int c = g_cnt[node];
#pragma unroll 8
    for (int k = 0; k < c; k++) {
        int2 sp = g_csr[o + k];                       // broadcast within half-warp
        float nrm = __int_as_float(sp.y);
        uint4 hv = g_hh[(long)sp.x * 16 + sub];       // 256B per half-warp
        fma8(hv, nrm, a);
    }

    float4 b0 = *(const float4*)(bias + sub * 8);
    float4 b1 = *(const float4*)(bias + sub * 8 + 4);
    float r0 = fmaxf(a[0] + b0.x, 0.f), r1 = fmaxf(a[1] + b0.y, 0.f);
    float r2 = fmaxf(a[2] + b0.z, 0.f), r3 = fmaxf(a[3] + b0.w, 0.f);
    float r4 = fmaxf(a[4] + b1.x, 0.f), r5 = fmaxf(a[5] + b1.y, 0.f);
    float r6 = fmaxf(a[6] + b1.z, 0.f), r7 = fmaxf(a[7] + b1.w, 0.f);
    __half2 p0 = __floats2half2_rn(r0, r1), p1 = __floats2half2_rn(r2, r3);
    __half2 p2 = __floats2half2_rn(r4, r5), p3 = __floats2half2_rn(r6, r7);
    uint4 u;
    u.x = *(unsigned*)&p0; u.y = *(unsigned*)&p1;
    u.z = *(unsigned*)&p2; u.w = *(unsigned*)&p3;
    g_a16[(long)node * 16 + sub] = u;
}

// ---------------- sparse aggregation, fp16, F=64 (final, fp32 out): 8 lanes/node ----------------
__global__ void __launch_bounds__(256) k_gather_h64(const float* __restrict__ bias,
                                                    float* __restrict__ outp, int n) {
    const int gt   = blockIdx.x * blockDim.x + threadIdx.x;
    const int node = gt >> 3;
    const int sub  = gt & 7;             // lane owns features 8*sub .. 8*sub+7
    if (node >= n) return;

    float di = g_dinv[node];
    float sl = di * di;

    float a[8];
    {
        uint4 sv = g_hh[(long)node * 8 + sub];
        __half2 h0 = *(__half2*)&sv.x, h1 = *(__half2*)&sv.y;
        __half2 h2 = *(__half2*)&sv.z, h3 = *(__half2*)&sv.w;
        float2 f0 = __half22float2(h0), f1 = __half22float2(h1);
        float2 f2 = __half22float2(h2), f3 = __half22float2(h3);
        a[0] = f0.x * sl; a[1] = f0.y * sl; a[2] = f1.x * sl; a[3] = f1.y * sl;
        a[4] = f2.x * sl; a[5] = f2.y * sl; a[6] = f3.x * sl; a[7] = f3.y * sl;
    }

    const int o = g_off[node];
    const int c = g_cnt[node];
#pragma unroll 8
    for (int k = 0; k < c; k++) {
        int2 sp = g_csr[o + k];
        float nrm = __int_as_float(sp.y);
        uint4 hv = g_hh[(long)sp.x * 8 + sub];
        fma8(hv, nrm, a);
    }

    float4 b0 = *(const float4*)(bias + sub * 8);
    float4 b1 = *(const float4*)(bias + sub * 8 + 4);
    float4 o0 = make_float4(a[0] + b0.x, a[1] + b0.y, a[2] + b0.z, a[3] + b0.w);
    float4 o1 = make_float4(a[4] + b1.x, a[5] + b1.y, a[6] + b1.z, a[7] + b1.w);
    *(float4*)(outp + (long)node * 64 + sub * 8)     = o0;
    *(float4*)(outp + (long)node * 64 + sub * 8 + 4) = o1;
}

// ---------------- host launcher ----------------
extern "C" void kernel_launch(void* const* d_in, const int* in_sizes, int n_in,
                              void* d_out, int out_size) {
    const float* x  = (const float*)d_in[0];
    const void*  ei = d_in[1];
    const float* ew = (const float*)d_in[2];
    const float* W1 = (const float*)d_in[3];
    const float* b1 = (const float*)d_in[4];
    const float* W2 = (const float*)d_in[5];
    const float* b2 = (const float*)d_in[6];
    const float* W3 = (const float*)d_in[7];
    const float* b3 = (const float*)d_in[8];

    const int n = in_sizes[0] / KDIM;   // 50000
    const int E = in_sizes[2];          // 1600000
    float* outp = (float*)d_out;

    const int TB = 256;
    const int nb_nodes = (n + TB - 1) / TB;
    const int nb_edge2 = ((E + 1) / 2 + TB - 1) / TB;
    const int nchunk   = (n + 511) / 512;
    const int nprep    = (n * 16 + 5120 + TB - 1) / TB;
    const int gemm_blocks   = (n + 63) / 64;
    const int gat128_blocks = (n * 16 + TB - 1) / TB;
    const int gat64_blocks  = (n * 8 + TB - 1) / TB;

    // ---- fork: side stream runs prep + GEMM1 concurrently with CSR build ----
    cudaStream_t s1;
    cudaStreamCreateWithFlags(&s1, cudaStreamNonBlocking);
    cudaEvent_t e0, e1;
    cudaEventCreateWithFlags(&e0, cudaEventDisableTiming);
    cudaEventCreateWithFlags(&e1, cudaEventDisableTiming);

    cudaEventRecord(e0, 0);
    cudaStreamWaitEvent(s1, e0, 0);

    k_prep<<<nprep, TB, 0, s1>>>((const float4*)x, (const float4*)W1,
                                 (const float4*)W2, (const float4*)W3, n);
    k_hgemm<128><<<gemm_blocks, 256, 0, s1>>>(0, n);

    k_init<<<nb_nodes, TB>>>(ei, n);
    k_edge_deg<<<nb_edge2, TB>>>(ei, ew, E, n);
    k_scan<<<nchunk, 512>>>(n);
    k_edge_fill<<<nb_edge2, TB>>>(ei, ew, E);

    cudaEventRecord(e1, s1);
    cudaStreamWaitEvent(0, e1, 0);

    // ---- layer 1 gather ----
    k_gather_h<<<gat128_blocks, TB>>>(b1, n);

    // ---- layer 2 ----
    k_hgemm<128><<<gemm_blocks, 256>>>(2048, n);
    k_gather_h<<<gat128_blocks, TB>>>(b2, n);

    // ---- layer 3 ----
    k_hgemm<64><<<gemm_blocks, 256>>>(4096, n);
    k_gather_h64<<<gat64_blocks, TB>>>(b3, outp, n);

    cudaEventDestroy(e0);
    cudaEventDestroy(e1);
    cudaStreamDestroy(s1);
}